// round 10
// baseline (speedup 1.0000x reference)
#include <cuda_runtime.h>
#include <cuda_fp16.h>
#include <cstdint>
#include <math.h>

#define FULL 0xffffffffu

// ===================== device globals =====================
__device__ __half g_Ure[256 * 256];        // U_re[i][k], K-major
__device__ __half g_Uim[256 * 256];        // U_im[i][k], K-major

// ===================== scalar fused-block sim (validated R1/R6) =====================
template<int CB, int TB>
__device__ __forceinline__ void apply_block(float (&re)[8], float (&im)[8],
                                            const float* cf, unsigned lane) {
    float cs = cf[0], ss = cf[1];
    float ar = cf[2], ai = cf[3], br = cf[4], bi = cf[5];
    if constexpr (TB >= 5) {
        static_assert(CB >= 5, "in-lane target gates have in-register control");
        constexpr int tm = 1 << (TB - 5);
#pragma unroll
        for (int r0 = 0; r0 < 8; r0++) {
            if (r0 & tm) continue;
            const int r1 = r0 | tm;
            float x0r = re[r0], x0i = im[r0], x1r = re[r1], x1i = im[r1];
            if (((r0 >> (CB - 5)) & 1) == 0) {
                re[r0] = cs * x0r - ss * x1r;  im[r0] = cs * x0i - ss * x1i;
                re[r1] = ss * x0r + cs * x1r;  im[r1] = ss * x0i + cs * x1i;
            } else {
                re[r0] = -br * x0r + bi * x0i + ar * x1r - ai * x1i;
                im[r0] = -br * x0i - bi * x0r + ar * x1i + ai * x1r;
                re[r1] =  ar * x0r - ai * x0i + br * x1r - bi * x1i;
                im[r1] =  ar * x0i + ai * x0r + br * x1i + bi * x1r;
            }
        }
    } else {
        const bool side = (lane >> TB) & 1;
        if constexpr (CB >= 5) {
            float Bs = side ? ss : -ss;
            float Ar = side ? br : -br;
            float Ai = side ? bi : -bi;
#pragma unroll
            for (int r = 0; r < 8; r++) {
                float pr = __shfl_xor_sync(FULL, re[r], 1 << TB);
                float pi = __shfl_xor_sync(FULL, im[r], 1 << TB);
                if (((r >> (CB - 5)) & 1) == 0) {
                    re[r] = cs * re[r] + Bs * pr;
                    im[r] = cs * im[r] + Bs * pi;
                } else {
                    float xr = re[r], xi = im[r];
                    re[r] = Ar * xr - Ai * xi + ar * pr - ai * pi;
                    im[r] = Ar * xi + Ai * xr + ar * pi + ai * pr;
                }
            }
        } else {
            const bool c = (lane >> CB) & 1;
            float Ar, Ai, Br, Bi;
            if (c) { Ar = side ? br : -br; Ai = side ? bi : -bi; Br = ar; Bi = ai; }
            else   { Ar = cs; Ai = 0.f;    Br = side ? ss : -ss; Bi = 0.f; }
#pragma unroll
            for (int r = 0; r < 8; r++) {
                float pr = __shfl_xor_sync(FULL, re[r], 1 << TB);
                float pi = __shfl_xor_sync(FULL, im[r], 1 << TB);
                float xr = re[r], xi = im[r];
                re[r] = Ar * xr - Ai * xi + Br * pr - Bi * pi;
                im[r] = Ar * xi + Ai * xr + Br * pi + Bi * pr;
            }
        }
    }
}

// build U columns (coef computation fused); one warp per basis column
__global__ void build_u(const float* __restrict__ conv,
                        const float* __restrict__ pool) {
    __shared__ float scf[21 * 6];
    {
        int t = threadIdx.x;
        if (t < 21) {
            float t0, t1, t2;
            if (t < 14)      { const float* p = conv + t * 3; t0 = p[0]; t1 = p[1]; t2 = p[2]; }
            else if (t < 18) { t0 = pool[0]; t1 = pool[1]; t2 = pool[2]; }
            else if (t < 20) { t0 = pool[3]; t1 = pool[4]; t2 = pool[5]; }
            else             { t0 = pool[6]; t1 = pool[7]; t2 = pool[8]; }
            float sg = 0.5f * (t1 + t2), dl = 0.5f * (t2 - t1);
            float cs = cosf(sg), ss = sinf(sg);
            float cd = cosf(dl), sd = sinf(dl);
            float cp = cosf(t0), sp = sinf(t0);
            float* o = scf + t * 6;
            o[0] = cs; o[1] = ss;
            o[2] = cp * cd; o[3] = sp * cd;
            o[4] = cp * sd; o[5] = sp * sd;
        }
    }
    __syncthreads();

    const int wid = threadIdx.x >> 5;
    const unsigned lane = threadIdx.x & 31;
    const int k = blockIdx.x * (blockDim.x >> 5) + wid;
    float re[8], im[8];
#pragma unroll
    for (int r = 0; r < 8; r++) {
        re[r] = (r == (k >> 5) && lane == (unsigned)(k & 31)) ? 1.f : 0.f;
        im[r] = 0.f;
    }
    apply_block<7, 6>(re, im, scf + 0 * 6, lane);
    apply_block<6, 5>(re, im, scf + 1 * 6, lane);
    apply_block<5, 4>(re, im, scf + 2 * 6, lane);
    apply_block<4, 3>(re, im, scf + 3 * 6, lane);
    apply_block<3, 2>(re, im, scf + 4 * 6, lane);
    apply_block<2, 1>(re, im, scf + 5 * 6, lane);
    apply_block<1, 0>(re, im, scf + 6 * 6, lane);
    apply_block<7, 6>(re, im, scf + 7 * 6, lane);
    apply_block<6, 5>(re, im, scf + 8 * 6, lane);
    apply_block<5, 4>(re, im, scf + 9 * 6, lane);
    apply_block<4, 3>(re, im, scf + 10 * 6, lane);
    apply_block<3, 2>(re, im, scf + 11 * 6, lane);
    apply_block<2, 1>(re, im, scf + 12 * 6, lane);
    apply_block<1, 0>(re, im, scf + 13 * 6, lane);
    apply_block<7, 3>(re, im, scf + 14 * 6, lane);
    apply_block<6, 2>(re, im, scf + 15 * 6, lane);
    apply_block<5, 1>(re, im, scf + 16 * 6, lane);
    apply_block<4, 0>(re, im, scf + 17 * 6, lane);
    apply_block<7, 5>(re, im, scf + 18 * 6, lane);
    apply_block<6, 4>(re, im, scf + 19 * 6, lane);
    apply_block<7, 6>(re, im, scf + 20 * 6, lane);
#pragma unroll
    for (int r = 0; r < 8; r++) {
        int i = (r << 5) | lane;
        g_Ure[i * 256 + k] = __float2half(re[r]);
        g_Uim[i * 256 + k] = __float2half(im[r]);
    }
}

// ===================== HMMA helpers =====================
__device__ __forceinline__ uint32_t smem_u32(const void* p) {
    uint32_t a;
    asm("{ .reg .u64 t; cvta.to.shared.u64 t, %1; cvt.u32.u64 %0, t; }" : "=r"(a) : "l"(p));
    return a;
}
__device__ __forceinline__ void ldsm_x4(uint32_t& r0, uint32_t& r1,
                                        uint32_t& r2, uint32_t& r3, uint32_t addr) {
    asm volatile("ldmatrix.sync.aligned.m8n8.x4.shared.b16 {%0,%1,%2,%3}, [%4];"
                 : "=r"(r0), "=r"(r1), "=r"(r2), "=r"(r3) : "r"(addr));
}
__device__ __forceinline__ void mma16816(float& c0, float& c1, float& c2, float& c3,
                                         uint32_t a0, uint32_t a1, uint32_t a2, uint32_t a3,
                                         uint32_t b0, uint32_t b1) {
    asm volatile("mma.sync.aligned.m16n8k16.row.col.f32.f16.f16.f32 "
                 "{%0,%1,%2,%3}, {%4,%5,%6,%7}, {%8,%9}, {%0,%1,%2,%3};"
                 : "+f"(c0), "+f"(c1), "+f"(c2), "+f"(c3)
                 : "r"(a0), "r"(a1), "r"(a2), "r"(a3), "r"(b0), "r"(b1));
}

// ===================== main GEMM kernel (M=16/warp, 4 CTAs/SM, oct B tiles) =====
static constexpr int BROW = 264;                         // halfs per smem row (256 + 8 pad)
static constexpr int SMEM_TOTAL = 64 * BROW * 2;         // 33792 bytes (oct tile)

__global__ void __launch_bounds__(128, 4)
qgemm(const float* __restrict__ x, float* __restrict__ out) {
    extern __shared__ __half smB[];
    const uint32_t smb = smem_u32(smB);
    const int tid  = threadIdx.x;
    const int wid  = tid >> 5;
    const int lane = tid & 31;
    const int quad = lane & 3;       // t%4
    const int qrow = lane >> 2;      // t/4

    // ---- A fragments: 2 row-sels (rows base+qrow, +8), 16 k-tiles (64 regs)
    const int base = (blockIdx.x * 4 + wid) * 16;
    uint32_t A2[2][16][2];
#pragma unroll
    for (int rs = 0; rs < 2; rs++) {
        const int row = base + qrow + rs * 8;
        const float4* xp = (const float4*)(x + (size_t)row * 8);
        float4 x0 = xp[0], x1 = xp[1];
        float xv[8] = {x0.x, x0.y, x0.z, x0.w, x1.x, x1.y, x1.z, x1.w};
        float c_[8], s_[8];
#pragma unroll
        for (int q = 0; q < 8; q++) __sincosf(0.5f * xv[q], &s_[q], &c_[q]);
        float hi16[16];
#pragma unroll
        for (int h = 0; h < 16; h++)
            hi16[h] = ((h & 8) ? s_[0] : c_[0]) * ((h & 4) ? s_[1] : c_[1]) *
                      ((h & 2) ? s_[2] : c_[2]) * ((h & 1) ? s_[3] : c_[3]);
        float q5 = (quad & 2) ? s_[5] : c_[5];
        float q6 = (quad & 1) ? s_[6] : c_[6];
        float m56 = q5 * q6;
        float l00 = c_[4] * m56 * c_[7], l01 = c_[4] * m56 * s_[7];
        float l10 = s_[4] * m56 * c_[7], l11 = s_[4] * m56 * s_[7];
#pragma unroll
        for (int kk = 0; kk < 16; kk++) {
            float h = hi16[kk];
            __half2 plo = __floats2half2_rn(h * l00, h * l01);
            __half2 phi = __floats2half2_rn(h * l10, h * l11);
            A2[rs][kk][0] = *(uint32_t*)&plo;
            A2[rs][kk][1] = *(uint32_t*)&phi;
        }
    }

    float z7a[2] = {0,0}, z4a[2] = {0,0}, z3a[2] = {0,0}, z2a[2] = {0,0};
    float Sa[2] = {0,0}, z1a[2] = {0,0}, z0a[2] = {0,0};

    // ldmatrix lane base: groups 0/1 = Ure k-lo/k-hi, 2/3 = Uim (rows +32)
    const int lgrp = lane >> 3, lrow = lane & 7;
    const uint32_t lbase = smb +
        (uint32_t)((((lgrp & 2) ? 32 : 0) + lrow) * BROW + (lgrp & 1) * 8) * 2;

    for (int oc = 0; oc < 8; oc++) {
        const int n0 = oc * 32;
        // ---- B oct: smem rows 0-31 = Ure[n0..n0+31], rows 32-63 = Uim[n0..]
#pragma unroll
        for (int j = 0; j < 16; j++) {
            int c = j * 128 + tid;            // 2048 uint4 chunks
            int row = c >> 5, kc = (c & 31) * 8;
            const __half* src = (row < 32) ? (g_Ure + (size_t)(n0 + row) * 256 + kc)
                                           : (g_Uim + (size_t)(n0 + row - 32) * 256 + kc);
            *(uint4*)(smB + row * BROW + kc) = *(const uint4*)src;
        }
        __syncthreads();

        float Sc[2] = {0,0};
#pragma unroll
        for (int nt = 0; nt < 4; nt++) {
            // split-K accumulators (even/odd kk): 4 indep MMA chains
            float cre_e[4] = {0,0,0,0}, cim_e[4] = {0,0,0,0};
            float cre_o[4] = {0,0,0,0}, cim_o[4] = {0,0,0,0};
            uint32_t bufA[4], bufB[4];
            ldsm_x4(bufA[0], bufA[1], bufA[2], bufA[3],
                    lbase + (uint32_t)(nt * 8 * BROW) * 2);
#pragma unroll
            for (int kk = 0; kk < 16; kk++) {
                uint32_t* cur = (kk & 1) ? bufB : bufA;
                uint32_t* nxt = (kk & 1) ? bufA : bufB;
                if (kk < 15)
                    ldsm_x4(nxt[0], nxt[1], nxt[2], nxt[3],
                            lbase + (uint32_t)(nt * 8 * BROW + (kk + 1) * 16) * 2);
                float* cr = (kk & 1) ? cre_o : cre_e;
                float* ci = (kk & 1) ? cim_o : cim_e;
                mma16816(cr[0], cr[1], cr[2], cr[3],
                         A2[0][kk][0], A2[1][kk][0], A2[0][kk][1], A2[1][kk][1],
                         cur[0], cur[1]);
                mma16816(ci[0], ci[1], ci[2], ci[3],
                         A2[0][kk][0], A2[1][kk][0], A2[0][kk][1], A2[1][kk][1],
                         cur[2], cur[3]);
            }
#pragma unroll
            for (int rs = 0; rs < 2; rs++) {
                float r0 = cre_e[2*rs]   + cre_o[2*rs];
                float r1 = cre_e[2*rs+1] + cre_o[2*rs+1];
                float i0 = cim_e[2*rs]   + cim_o[2*rs];
                float i1 = cim_e[2*rs+1] + cim_o[2*rs+1];
                float p0 = r0 * r0 + i0 * i0;
                float p1 = r1 * r1 + i1 * i1;
                float d = p0 - p1, s = p0 + p1;
                z7a[rs] += d;
                Sc[rs] += s;
                z4a[rs] += (nt & 1) ? -s : s;
                z3a[rs] += (nt & 2) ? -s : s;
            }
        }
#pragma unroll
        for (int rs = 0; rs < 2; rs++) {
            Sa[rs] += Sc[rs];
            z2a[rs] += (oc & 1) ? -Sc[rs] : Sc[rs];
            z1a[rs] += (oc & 2) ? -Sc[rs] : Sc[rs];
            z0a[rs] += (oc & 4) ? -Sc[rs] : Sc[rs];
        }
        __syncthreads();
    }

    // ---- finalize: z6/z5 via lane-constant signs on S; butterfly over quad lanes
#pragma unroll
    for (int rs = 0; rs < 2; rs++) {
        float z[8];
        z[0] = z0a[rs]; z[1] = z1a[rs]; z[2] = z2a[rs]; z[3] = z3a[rs];
        z[4] = z4a[rs];
        z[5] = ((quad >> 1) & 1) ? -Sa[rs] : Sa[rs];
        z[6] = (quad & 1) ? -Sa[rs] : Sa[rs];
        z[7] = z7a[rs];
#pragma unroll
        for (int q = 0; q < 8; q++) {
            z[q] += __shfl_xor_sync(FULL, z[q], 1);
            z[q] += __shfl_xor_sync(FULL, z[q], 2);
        }
        const int row = base + qrow + rs * 8;
        float2* o = (float2*)(out + (size_t)row * 8 + 2 * quad);
        *o = make_float2(z[2 * quad], z[2 * quad + 1]);
    }
}

// ===================== host launcher =====================
extern "C" void kernel_launch(void* const* d_in, const int* in_sizes, int n_in,
                              void* d_out, int out_size) {
    const float* x    = (const float*)d_in[0];
    const float* conv = (const float*)d_in[1];
    const float* pool = (const float*)d_in[2];
    float* out = (float*)d_out;

    int nb = in_sizes[0] / 8;           // 65536
    int tiles = nb / 64;                // 1024 CTAs (64 rows each)

    build_u<<<128, 64>>>(conv, pool);

    cudaFuncSetAttribute(qgemm, cudaFuncAttributeMaxDynamicSharedMemorySize, SMEM_TOTAL);
    qgemm<<<tiles, 128, SMEM_TOTAL>>>(x, out);
}

// round 11
// speedup vs baseline: 1.0331x; 1.0331x over previous
#include <cuda_runtime.h>
#include <cuda_fp16.h>
#include <cstdint>
#include <math.h>

#define FULL 0xffffffffu

// ===================== device globals =====================
__device__ __half g_Ure[256 * 256];        // U_re[i][k], K-major
__device__ __half g_Uim[256 * 256];        // U_im[i][k], K-major

// ===================== scalar fused-block sim (validated R1/R6) =====================
template<int CB, int TB>
__device__ __forceinline__ void apply_block(float (&re)[8], float (&im)[8],
                                            const float* cf, unsigned lane) {
    float cs = cf[0], ss = cf[1];
    float ar = cf[2], ai = cf[3], br = cf[4], bi = cf[5];
    if constexpr (TB >= 5) {
        static_assert(CB >= 5, "in-lane target gates have in-register control");
        constexpr int tm = 1 << (TB - 5);
#pragma unroll
        for (int r0 = 0; r0 < 8; r0++) {
            if (r0 & tm) continue;
            const int r1 = r0 | tm;
            float x0r = re[r0], x0i = im[r0], x1r = re[r1], x1i = im[r1];
            if (((r0 >> (CB - 5)) & 1) == 0) {
                re[r0] = cs * x0r - ss * x1r;  im[r0] = cs * x0i - ss * x1i;
                re[r1] = ss * x0r + cs * x1r;  im[r1] = ss * x0i + cs * x1i;
            } else {
                re[r0] = -br * x0r + bi * x0i + ar * x1r - ai * x1i;
                im[r0] = -br * x0i - bi * x0r + ar * x1i + ai * x1r;
                re[r1] =  ar * x0r - ai * x0i + br * x1r - bi * x1i;
                im[r1] =  ar * x0i + ai * x0r + br * x1i + bi * x1r;
            }
        }
    } else {
        const bool side = (lane >> TB) & 1;
        if constexpr (CB >= 5) {
            float Bs = side ? ss : -ss;
            float Ar = side ? br : -br;
            float Ai = side ? bi : -bi;
#pragma unroll
            for (int r = 0; r < 8; r++) {
                float pr = __shfl_xor_sync(FULL, re[r], 1 << TB);
                float pi = __shfl_xor_sync(FULL, im[r], 1 << TB);
                if (((r >> (CB - 5)) & 1) == 0) {
                    re[r] = cs * re[r] + Bs * pr;
                    im[r] = cs * im[r] + Bs * pi;
                } else {
                    float xr = re[r], xi = im[r];
                    re[r] = Ar * xr - Ai * xi + ar * pr - ai * pi;
                    im[r] = Ar * xi + Ai * xr + ar * pi + ai * pr;
                }
            }
        } else {
            const bool c = (lane >> CB) & 1;
            float Ar, Ai, Br, Bi;
            if (c) { Ar = side ? br : -br; Ai = side ? bi : -bi; Br = ar; Bi = ai; }
            else   { Ar = cs; Ai = 0.f;    Br = side ? ss : -ss; Bi = 0.f; }
#pragma unroll
            for (int r = 0; r < 8; r++) {
                float pr = __shfl_xor_sync(FULL, re[r], 1 << TB);
                float pi = __shfl_xor_sync(FULL, im[r], 1 << TB);
                float xr = re[r], xi = im[r];
                re[r] = Ar * xr - Ai * xi + Br * pr - Bi * pi;
                im[r] = Ar * xi + Ai * xr + Br * pi + Bi * pr;
            }
        }
    }
}

// build U columns (coef computation fused); one warp per basis column
__global__ void build_u(const float* __restrict__ conv,
                        const float* __restrict__ pool) {
    __shared__ float scf[21 * 6];
    {
        int t = threadIdx.x;
        if (t < 21) {
            float t0, t1, t2;
            if (t < 14)      { const float* p = conv + t * 3; t0 = p[0]; t1 = p[1]; t2 = p[2]; }
            else if (t < 18) { t0 = pool[0]; t1 = pool[1]; t2 = pool[2]; }
            else if (t < 20) { t0 = pool[3]; t1 = pool[4]; t2 = pool[5]; }
            else             { t0 = pool[6]; t1 = pool[7]; t2 = pool[8]; }
            float sg = 0.5f * (t1 + t2), dl = 0.5f * (t2 - t1);
            float cs = cosf(sg), ss = sinf(sg);
            float cd = cosf(dl), sd = sinf(dl);
            float cp = cosf(t0), sp = sinf(t0);
            float* o = scf + t * 6;
            o[0] = cs; o[1] = ss;
            o[2] = cp * cd; o[3] = sp * cd;
            o[4] = cp * sd; o[5] = sp * sd;
        }
    }
    __syncthreads();

    // let the dependent qgemm grid launch now; it synchronizes on our completion
    cudaTriggerProgrammaticLaunchCompletion();

    const int wid = threadIdx.x >> 5;
    const unsigned lane = threadIdx.x & 31;
    const int k = blockIdx.x * (blockDim.x >> 5) + wid;
    float re[8], im[8];
#pragma unroll
    for (int r = 0; r < 8; r++) {
        re[r] = (r == (k >> 5) && lane == (unsigned)(k & 31)) ? 1.f : 0.f;
        im[r] = 0.f;
    }
    apply_block<7, 6>(re, im, scf + 0 * 6, lane);
    apply_block<6, 5>(re, im, scf + 1 * 6, lane);
    apply_block<5, 4>(re, im, scf + 2 * 6, lane);
    apply_block<4, 3>(re, im, scf + 3 * 6, lane);
    apply_block<3, 2>(re, im, scf + 4 * 6, lane);
    apply_block<2, 1>(re, im, scf + 5 * 6, lane);
    apply_block<1, 0>(re, im, scf + 6 * 6, lane);
    apply_block<7, 6>(re, im, scf + 7 * 6, lane);
    apply_block<6, 5>(re, im, scf + 8 * 6, lane);
    apply_block<5, 4>(re, im, scf + 9 * 6, lane);
    apply_block<4, 3>(re, im, scf + 10 * 6, lane);
    apply_block<3, 2>(re, im, scf + 11 * 6, lane);
    apply_block<2, 1>(re, im, scf + 12 * 6, lane);
    apply_block<1, 0>(re, im, scf + 13 * 6, lane);
    apply_block<7, 3>(re, im, scf + 14 * 6, lane);
    apply_block<6, 2>(re, im, scf + 15 * 6, lane);
    apply_block<5, 1>(re, im, scf + 16 * 6, lane);
    apply_block<4, 0>(re, im, scf + 17 * 6, lane);
    apply_block<7, 5>(re, im, scf + 18 * 6, lane);
    apply_block<6, 4>(re, im, scf + 19 * 6, lane);
    apply_block<7, 6>(re, im, scf + 20 * 6, lane);
#pragma unroll
    for (int r = 0; r < 8; r++) {
        int i = (r << 5) | lane;
        g_Ure[i * 256 + k] = __float2half(re[r]);
        g_Uim[i * 256 + k] = __float2half(im[r]);
    }
}

// ===================== HMMA helpers =====================
__device__ __forceinline__ uint32_t smem_u32(const void* p) {
    uint32_t a;
    asm("{ .reg .u64 t; cvta.to.shared.u64 t, %1; cvt.u32.u64 %0, t; }" : "=r"(a) : "l"(p));
    return a;
}
__device__ __forceinline__ void ldsm_x4(uint32_t& r0, uint32_t& r1,
                                        uint32_t& r2, uint32_t& r3, uint32_t addr) {
    asm volatile("ldmatrix.sync.aligned.m8n8.x4.shared.b16 {%0,%1,%2,%3}, [%4];"
                 : "=r"(r0), "=r"(r1), "=r"(r2), "=r"(r3) : "r"(addr));
}
__device__ __forceinline__ void mma16816(float& c0, float& c1, float& c2, float& c3,
                                         uint32_t a0, uint32_t a1, uint32_t a2, uint32_t a3,
                                         uint32_t b0, uint32_t b1) {
    asm volatile("mma.sync.aligned.m16n8k16.row.col.f32.f16.f16.f32 "
                 "{%0,%1,%2,%3}, {%4,%5,%6,%7}, {%8,%9}, {%0,%1,%2,%3};"
                 : "+f"(c0), "+f"(c1), "+f"(c2), "+f"(c3)
                 : "r"(a0), "r"(a1), "r"(a2), "r"(a3), "r"(b0), "r"(b1));
}

// ===================== main GEMM kernel (M=32 per warp, split-K ILP) =====================
static constexpr int BROW = 264;                       // halfs per smem row (256 + 8 pad)
static constexpr int SMEM_TOTAL = 128 * BROW * 2;      // 67584 bytes

__global__ void __launch_bounds__(128, 2)
qgemm(const float* __restrict__ x, float* __restrict__ out) {
    extern __shared__ __half smB[];
    const uint32_t smb = smem_u32(smB);
    const int tid  = threadIdx.x;
    const int wid  = tid >> 5;
    const int lane = tid & 31;
    const int quad = lane & 3;       // t%4
    const int qrow = lane >> 2;      // t/4

    // ---- A fragments in registers (does NOT depend on build_u output)
    const int base = (blockIdx.x * 4 + wid) * 32;
    uint32_t A2[4][16][2];
#pragma unroll
    for (int rs = 0; rs < 4; rs++) {
        const int row = base + qrow + rs * 8;
        const float4* xp = (const float4*)(x + (size_t)row * 8);
        float4 x0 = xp[0], x1 = xp[1];
        float xv[8] = {x0.x, x0.y, x0.z, x0.w, x1.x, x1.y, x1.z, x1.w};
        float c_[8], s_[8];
#pragma unroll
        for (int q = 0; q < 8; q++) __sincosf(0.5f * xv[q], &s_[q], &c_[q]);
        float hi16[16];
#pragma unroll
        for (int h = 0; h < 16; h++)
            hi16[h] = ((h & 8) ? s_[0] : c_[0]) * ((h & 4) ? s_[1] : c_[1]) *
                      ((h & 2) ? s_[2] : c_[2]) * ((h & 1) ? s_[3] : c_[3]);
        float q5 = (quad & 2) ? s_[5] : c_[5];
        float q6 = (quad & 1) ? s_[6] : c_[6];
        float m56 = q5 * q6;
        float l00 = c_[4] * m56 * c_[7], l01 = c_[4] * m56 * s_[7];
        float l10 = s_[4] * m56 * c_[7], l11 = s_[4] * m56 * s_[7];
#pragma unroll
        for (int kk = 0; kk < 16; kk++) {
            float h = hi16[kk];
            __half2 plo = __floats2half2_rn(h * l00, h * l01);
            __half2 phi = __floats2half2_rn(h * l10, h * l11);
            A2[rs][kk][0] = *(uint32_t*)&plo;
            A2[rs][kk][1] = *(uint32_t*)&phi;
        }
    }

    // wait for build_u to fully complete before touching g_Ure / g_Uim
    cudaGridDependencySynchronize();

    float z7a[4] = {0,0,0,0}, z4a[4] = {0,0,0,0}, z3a[4] = {0,0,0,0}, z2a[4] = {0,0,0,0};
    float Sa[4] = {0,0,0,0}, z1a[4] = {0,0,0,0}, z0a[4] = {0,0,0,0};

    const int lgrp = lane >> 3, lrow = lane & 7;
    const uint32_t lbase = smb +
        (uint32_t)((((lgrp & 2) ? 64 : 0) + lrow) * BROW + (lgrp & 1) * 8) * 2;

    for (int it = 0; it < 4; it++) {
        const int n0 = it * 64;
        // ---- B chunk: smem rows 0-63 = Ure[n0..], 64-127 = Uim[n0..]
#pragma unroll
        for (int j = 0; j < 32; j++) {
            int c = j * 128 + tid;
            int row = c >> 5, kc = (c & 31) * 8;
            const __half* src = (row < 64) ? (g_Ure + (size_t)(n0 + row) * 256 + kc)
                                           : (g_Uim + (size_t)(n0 + row - 64) * 256 + kc);
            *(uint4*)(smB + row * BROW + kc) = *(const uint4*)src;
        }
        __syncthreads();

        float Sc[4] = {0,0,0,0};
#pragma unroll
        for (int nt = 0; nt < 8; nt++) {
            // split-K accumulators: even kk -> *_e, odd kk -> *_o  (8 indep chains)
            float cre_e[8] = {0,0,0,0,0,0,0,0}, cim_e[8] = {0,0,0,0,0,0,0,0};
            float cre_o[8] = {0,0,0,0,0,0,0,0}, cim_o[8] = {0,0,0,0,0,0,0,0};
            uint32_t bufA[4], bufB[4];
            ldsm_x4(bufA[0], bufA[1], bufA[2], bufA[3],
                    lbase + (uint32_t)(nt * 8 * BROW) * 2);
#pragma unroll
            for (int kk = 0; kk < 16; kk++) {
                uint32_t* cur = (kk & 1) ? bufB : bufA;
                uint32_t* nxt = (kk & 1) ? bufA : bufB;
                if (kk < 15)
                    ldsm_x4(nxt[0], nxt[1], nxt[2], nxt[3],
                            lbase + (uint32_t)(nt * 8 * BROW + (kk + 1) * 16) * 2);
                float* cr = (kk & 1) ? cre_o : cre_e;
                float* ci = (kk & 1) ? cim_o : cim_e;
                mma16816(cr[0], cr[1], cr[2], cr[3],
                         A2[0][kk][0], A2[1][kk][0], A2[0][kk][1], A2[1][kk][1],
                         cur[0], cur[1]);
                mma16816(cr[4], cr[5], cr[6], cr[7],
                         A2[2][kk][0], A2[3][kk][0], A2[2][kk][1], A2[3][kk][1],
                         cur[0], cur[1]);
                mma16816(ci[0], ci[1], ci[2], ci[3],
                         A2[0][kk][0], A2[1][kk][0], A2[0][kk][1], A2[1][kk][1],
                         cur[2], cur[3]);
                mma16816(ci[4], ci[5], ci[6], ci[7],
                         A2[2][kk][0], A2[3][kk][0], A2[2][kk][1], A2[3][kk][1],
                         cur[2], cur[3]);
            }
#pragma unroll
            for (int rs = 0; rs < 4; rs++) {
                float r0 = cre_e[2*rs]   + cre_o[2*rs];
                float r1 = cre_e[2*rs+1] + cre_o[2*rs+1];
                float i0 = cim_e[2*rs]   + cim_o[2*rs];
                float i1 = cim_e[2*rs+1] + cim_o[2*rs+1];
                float p0 = r0 * r0 + i0 * i0;
                float p1 = r1 * r1 + i1 * i1;
                float d = p0 - p1, s = p0 + p1;
                z7a[rs] += d;
                Sc[rs] += s;
                z4a[rs] += (nt & 1) ? -s : s;
                z3a[rs] += (nt & 2) ? -s : s;
                z2a[rs] += (nt & 4) ? -s : s;
            }
        }
#pragma unroll
        for (int rs = 0; rs < 4; rs++) {
            Sa[rs] += Sc[rs];
            z1a[rs] += (it & 1) ? -Sc[rs] : Sc[rs];
            z0a[rs] += (it & 2) ? -Sc[rs] : Sc[rs];
        }
        __syncthreads();
    }

    // ---- finalize: z6/z5 via lane-constant signs on S; butterfly over quad lanes
#pragma unroll
    for (int rs = 0; rs < 4; rs++) {
        float z[8];
        z[0] = z0a[rs]; z[1] = z1a[rs]; z[2] = z2a[rs]; z[3] = z3a[rs];
        z[4] = z4a[rs];
        z[5] = ((quad >> 1) & 1) ? -Sa[rs] : Sa[rs];
        z[6] = (quad & 1) ? -Sa[rs] : Sa[rs];
        z[7] = z7a[rs];
#pragma unroll
        for (int q = 0; q < 8; q++) {
            z[q] += __shfl_xor_sync(FULL, z[q], 1);
            z[q] += __shfl_xor_sync(FULL, z[q], 2);
        }
        const int row = base + qrow + rs * 8;
        float2* o = (float2*)(out + (size_t)row * 8 + 2 * quad);
        *o = make_float2(z[2 * quad], z[2 * quad + 1]);
    }
}

// ===================== host launcher =====================
extern "C" void kernel_launch(void* const* d_in, const int* in_sizes, int n_in,
                              void* d_out, int out_size) {
    const float* x    = (const float*)d_in[0];
    const float* conv = (const float*)d_in[1];
    const float* pool = (const float*)d_in[2];
    float* out = (float*)d_out;

    int nb = in_sizes[0] / 8;           // 65536
    int tiles = nb / 128;               // 512

    build_u<<<128, 64>>>(conv, pool);

    static bool attr_set = false;
    if (!attr_set) {
        cudaFuncSetAttribute(qgemm, cudaFuncAttributeMaxDynamicSharedMemorySize, SMEM_TOTAL);
        attr_set = true;
    }

    // PDL launch: qgemm may start (building A fragments) while build_u runs;
    // cudaGridDependencySynchronize() inside qgemm orders the U reads.
    cudaLaunchConfig_t cfg = {};
    cfg.gridDim = dim3((unsigned)tiles, 1, 1);
    cfg.blockDim = dim3(128, 1, 1);
    cfg.dynamicSmemBytes = SMEM_TOTAL;
    cfg.stream = 0;
    cudaLaunchAttribute attrs[1];
    attrs[0].id = cudaLaunchAttributeProgrammaticStreamSerialization;
    attrs[0].val.programmaticStreamSerializationAllowed = 1;
    cfg.attrs = attrs;
    cfg.numAttrs = 1;
    cudaLaunchKernelEx(&cfg, qgemm, x, out);
}

// round 12
// speedup vs baseline: 1.0684x; 1.0342x over previous
#include <cuda_runtime.h>
#include <cuda_fp16.h>
#include <cstdint>
#include <math.h>

#define FULL 0xffffffffu

// ===================== device globals =====================
__device__ __half g_Ure[256 * 256];        // U_re[i][k], K-major
__device__ __half g_Uim[256 * 256];        // U_im[i][k], K-major

// ===================== scalar fused-block sim (validated R1/R6) =====================
template<int CB, int TB>
__device__ __forceinline__ void apply_block(float (&re)[8], float (&im)[8],
                                            const float* cf, unsigned lane) {
    float cs = cf[0], ss = cf[1];
    float ar = cf[2], ai = cf[3], br = cf[4], bi = cf[5];
    if constexpr (TB >= 5) {
        static_assert(CB >= 5, "in-lane target gates have in-register control");
        constexpr int tm = 1 << (TB - 5);
#pragma unroll
        for (int r0 = 0; r0 < 8; r0++) {
            if (r0 & tm) continue;
            const int r1 = r0 | tm;
            float x0r = re[r0], x0i = im[r0], x1r = re[r1], x1i = im[r1];
            if (((r0 >> (CB - 5)) & 1) == 0) {
                re[r0] = cs * x0r - ss * x1r;  im[r0] = cs * x0i - ss * x1i;
                re[r1] = ss * x0r + cs * x1r;  im[r1] = ss * x0i + cs * x1i;
            } else {
                re[r0] = -br * x0r + bi * x0i + ar * x1r - ai * x1i;
                im[r0] = -br * x0i - bi * x0r + ar * x1i + ai * x1r;
                re[r1] =  ar * x0r - ai * x0i + br * x1r - bi * x1i;
                im[r1] =  ar * x0i + ai * x0r + br * x1i + bi * x1r;
            }
        }
    } else {
        const bool side = (lane >> TB) & 1;
        if constexpr (CB >= 5) {
            float Bs = side ? ss : -ss;
            float Ar = side ? br : -br;
            float Ai = side ? bi : -bi;
#pragma unroll
            for (int r = 0; r < 8; r++) {
                float pr = __shfl_xor_sync(FULL, re[r], 1 << TB);
                float pi = __shfl_xor_sync(FULL, im[r], 1 << TB);
                if (((r >> (CB - 5)) & 1) == 0) {
                    re[r] = cs * re[r] + Bs * pr;
                    im[r] = cs * im[r] + Bs * pi;
                } else {
                    float xr = re[r], xi = im[r];
                    re[r] = Ar * xr - Ai * xi + ar * pr - ai * pi;
                    im[r] = Ar * xi + Ai * xr + ar * pi + ai * pr;
                }
            }
        } else {
            const bool c = (lane >> CB) & 1;
            float Ar, Ai, Br, Bi;
            if (c) { Ar = side ? br : -br; Ai = side ? bi : -bi; Br = ar; Bi = ai; }
            else   { Ar = cs; Ai = 0.f;    Br = side ? ss : -ss; Bi = 0.f; }
#pragma unroll
            for (int r = 0; r < 8; r++) {
                float pr = __shfl_xor_sync(FULL, re[r], 1 << TB);
                float pi = __shfl_xor_sync(FULL, im[r], 1 << TB);
                float xr = re[r], xi = im[r];
                re[r] = Ar * xr - Ai * xi + Br * pr - Bi * pi;
                im[r] = Ar * xi + Ai * xr + Br * pi + Bi * pr;
            }
        }
    }
}

// build U columns (coef computation fused); one warp per basis column
__global__ void build_u(const float* __restrict__ conv,
                        const float* __restrict__ pool) {
    __shared__ float scf[21 * 6];
    {
        int t = threadIdx.x;
        if (t < 21) {
            float t0, t1, t2;
            if (t < 14)      { const float* p = conv + t * 3; t0 = p[0]; t1 = p[1]; t2 = p[2]; }
            else if (t < 18) { t0 = pool[0]; t1 = pool[1]; t2 = pool[2]; }
            else if (t < 20) { t0 = pool[3]; t1 = pool[4]; t2 = pool[5]; }
            else             { t0 = pool[6]; t1 = pool[7]; t2 = pool[8]; }
            float sg = 0.5f * (t1 + t2), dl = 0.5f * (t2 - t1);
            float cs = cosf(sg), ss = sinf(sg);
            float cd = cosf(dl), sd = sinf(dl);
            float cp = cosf(t0), sp = sinf(t0);
            float* o = scf + t * 6;
            o[0] = cs; o[1] = ss;
            o[2] = cp * cd; o[3] = sp * cd;
            o[4] = cp * sd; o[5] = sp * sd;
        }
    }
    __syncthreads();

    // let the dependent qgemm grid launch now; it synchronizes on our completion
    cudaTriggerProgrammaticLaunchCompletion();

    const int wid = threadIdx.x >> 5;
    const unsigned lane = threadIdx.x & 31;
    const int k = blockIdx.x * (blockDim.x >> 5) + wid;
    float re[8], im[8];
#pragma unroll
    for (int r = 0; r < 8; r++) {
        re[r] = (r == (k >> 5) && lane == (unsigned)(k & 31)) ? 1.f : 0.f;
        im[r] = 0.f;
    }
    apply_block<7, 6>(re, im, scf + 0 * 6, lane);
    apply_block<6, 5>(re, im, scf + 1 * 6, lane);
    apply_block<5, 4>(re, im, scf + 2 * 6, lane);
    apply_block<4, 3>(re, im, scf + 3 * 6, lane);
    apply_block<3, 2>(re, im, scf + 4 * 6, lane);
    apply_block<2, 1>(re, im, scf + 5 * 6, lane);
    apply_block<1, 0>(re, im, scf + 6 * 6, lane);
    apply_block<7, 6>(re, im, scf + 7 * 6, lane);
    apply_block<6, 5>(re, im, scf + 8 * 6, lane);
    apply_block<5, 4>(re, im, scf + 9 * 6, lane);
    apply_block<4, 3>(re, im, scf + 10 * 6, lane);
    apply_block<3, 2>(re, im, scf + 11 * 6, lane);
    apply_block<2, 1>(re, im, scf + 12 * 6, lane);
    apply_block<1, 0>(re, im, scf + 13 * 6, lane);
    apply_block<7, 3>(re, im, scf + 14 * 6, lane);
    apply_block<6, 2>(re, im, scf + 15 * 6, lane);
    apply_block<5, 1>(re, im, scf + 16 * 6, lane);
    apply_block<4, 0>(re, im, scf + 17 * 6, lane);
    apply_block<7, 5>(re, im, scf + 18 * 6, lane);
    apply_block<6, 4>(re, im, scf + 19 * 6, lane);
    apply_block<7, 6>(re, im, scf + 20 * 6, lane);
#pragma unroll
    for (int r = 0; r < 8; r++) {
        int i = (r << 5) | lane;
        g_Ure[i * 256 + k] = __float2half(re[r]);
        g_Uim[i * 256 + k] = __float2half(im[r]);
    }
}

// ===================== HMMA helpers =====================
__device__ __forceinline__ uint32_t smem_u32(const void* p) {
    uint32_t a;
    asm("{ .reg .u64 t; cvta.to.shared.u64 t, %1; cvt.u32.u64 %0, t; }" : "=r"(a) : "l"(p));
    return a;
}
__device__ __forceinline__ void ldsm_x4(uint32_t& r0, uint32_t& r1,
                                        uint32_t& r2, uint32_t& r3, uint32_t addr) {
    asm volatile("ldmatrix.sync.aligned.m8n8.x4.shared.b16 {%0,%1,%2,%3}, [%4];"
                 : "=r"(r0), "=r"(r1), "=r"(r2), "=r"(r3) : "r"(addr));
}
__device__ __forceinline__ void mma16816(float& c0, float& c1, float& c2, float& c3,
                                         uint32_t a0, uint32_t a1, uint32_t a2, uint32_t a3,
                                         uint32_t b0, uint32_t b1) {
    asm volatile("mma.sync.aligned.m16n8k16.row.col.f32.f16.f16.f32 "
                 "{%0,%1,%2,%3}, {%4,%5,%6,%7}, {%8,%9}, {%0,%1,%2,%3};"
                 : "+f"(c0), "+f"(c1), "+f"(c2), "+f"(c3)
                 : "r"(a0), "r"(a1), "r"(a2), "r"(a3), "r"(b0), "r"(b1));
}

// ===================== main GEMM kernel =====================
// Work unit = (tile t, quarter q): tile = 128 batch rows, quarter = 64 output cols.
// 512 tiles x 4 quarters = 2048 units over a fixed grid of 296 CTAs (98.8% balance).
static constexpr int BROW = 264;                       // halfs per smem row (256 + 8 pad)
static constexpr int SMEM_TOTAL = 128 * BROW * 2;      // 67584 bytes
static constexpr int NCTA = 296;                       // 148 SMs x 2 CTAs
static constexpr int NUNITS = 2048;
static constexpr int CHUNK_HI = (NUNITS + NCTA - 1) / NCTA;            // 7
static constexpr int NHI = NUNITS - (CHUNK_HI - 1) * NCTA;             // 272 CTAs get 7

__global__ void __launch_bounds__(128, 2)
qgemm(const float* __restrict__ x, float* __restrict__ out) {
    extern __shared__ __half smB[];
    const uint32_t smb = smem_u32(smB);
    const int tid  = threadIdx.x;
    const int wid  = tid >> 5;
    const int lane = tid & 31;
    const int quad = lane & 3;       // t%4
    const int qrow = lane >> 2;      // t/4

    // static contiguous unit chunk for this CTA
    int myStart, myCount;
    if (blockIdx.x < NHI) { myStart = blockIdx.x * CHUNK_HI; myCount = CHUNK_HI; }
    else {
        myStart = NHI * CHUNK_HI + (blockIdx.x - NHI) * (CHUNK_HI - 1);
        myCount = CHUNK_HI - 1;
    }

    const int lgrp = lane >> 3, lrow = lane & 7;
    const uint32_t lbase = smb +
        (uint32_t)((((lgrp & 2) ? 64 : 0) + lrow) * BROW + (lgrp & 1) * 8) * 2;

    uint32_t A2[4][16][2];
    int last_t = -1;
    bool synced = false;

    for (int u = myStart; u < myStart + myCount; u++) {
        const int t = u >> 2, q = u & 3;
        const int base = (t * 4 + wid) * 32;

        // ---- (re)build A fragments when the tile changes (indep of build_u)
        if (t != last_t) {
            last_t = t;
#pragma unroll
            for (int rs = 0; rs < 4; rs++) {
                const int row = base + qrow + rs * 8;
                const float4* xp = (const float4*)(x + (size_t)row * 8);
                float4 x0 = xp[0], x1 = xp[1];
                float xv[8] = {x0.x, x0.y, x0.z, x0.w, x1.x, x1.y, x1.z, x1.w};
                float c_[8], s_[8];
#pragma unroll
                for (int qq = 0; qq < 8; qq++) __sincosf(0.5f * xv[qq], &s_[qq], &c_[qq]);
                float hi16[16];
#pragma unroll
                for (int h = 0; h < 16; h++)
                    hi16[h] = ((h & 8) ? s_[0] : c_[0]) * ((h & 4) ? s_[1] : c_[1]) *
                              ((h & 2) ? s_[2] : c_[2]) * ((h & 1) ? s_[3] : c_[3]);
                float q5 = (quad & 2) ? s_[5] : c_[5];
                float q6 = (quad & 1) ? s_[6] : c_[6];
                float m56 = q5 * q6;
                float l00 = c_[4] * m56 * c_[7], l01 = c_[4] * m56 * s_[7];
                float l10 = s_[4] * m56 * c_[7], l11 = s_[4] * m56 * s_[7];
#pragma unroll
                for (int kk = 0; kk < 16; kk++) {
                    float h = hi16[kk];
                    __half2 plo = __floats2half2_rn(h * l00, h * l01);
                    __half2 phi = __floats2half2_rn(h * l10, h * l11);
                    A2[rs][kk][0] = *(uint32_t*)&plo;
                    A2[rs][kk][1] = *(uint32_t*)&phi;
                }
            }
        }

        // wait for build_u completion before first U read (overlaps A build above)
        if (!synced) { cudaGridDependencySynchronize(); synced = true; }

        // ---- B quarter q: smem rows 0-63 = Ure[n0..], 64-127 = Uim[n0..]
        const int n0 = q * 64;
#pragma unroll
        for (int j = 0; j < 32; j++) {
            int c = j * 128 + tid;
            int row = c >> 5, kc = (c & 31) * 8;
            const __half* src = (row < 64) ? (g_Ure + (size_t)(n0 + row) * 256 + kc)
                                           : (g_Uim + (size_t)(n0 + row - 64) * 256 + kc);
            *(uint4*)(smB + row * BROW + kc) = *(const uint4*)src;
        }
        __syncthreads();

        // ---- mainloop over the 8 n-tiles of this quarter
        float z7a[4] = {0,0,0,0}, z4a[4] = {0,0,0,0}, z3a[4] = {0,0,0,0},
              z2a[4] = {0,0,0,0}, Sc[4] = {0,0,0,0};
#pragma unroll
        for (int nt = 0; nt < 8; nt++) {
            float cre_e[8] = {0,0,0,0,0,0,0,0}, cim_e[8] = {0,0,0,0,0,0,0,0};
            float cre_o[8] = {0,0,0,0,0,0,0,0}, cim_o[8] = {0,0,0,0,0,0,0,0};
            uint32_t bufA[4], bufB[4];
            ldsm_x4(bufA[0], bufA[1], bufA[2], bufA[3],
                    lbase + (uint32_t)(nt * 8 * BROW) * 2);
#pragma unroll
            for (int kk = 0; kk < 16; kk++) {
                uint32_t* cur = (kk & 1) ? bufB : bufA;
                uint32_t* nxt = (kk & 1) ? bufA : bufB;
                if (kk < 15)
                    ldsm_x4(nxt[0], nxt[1], nxt[2], nxt[3],
                            lbase + (uint32_t)(nt * 8 * BROW + (kk + 1) * 16) * 2);
                float* cr = (kk & 1) ? cre_o : cre_e;
                float* ci = (kk & 1) ? cim_o : cim_e;
                mma16816(cr[0], cr[1], cr[2], cr[3],
                         A2[0][kk][0], A2[1][kk][0], A2[0][kk][1], A2[1][kk][1],
                         cur[0], cur[1]);
                mma16816(cr[4], cr[5], cr[6], cr[7],
                         A2[2][kk][0], A2[3][kk][0], A2[2][kk][1], A2[3][kk][1],
                         cur[0], cur[1]);
                mma16816(ci[0], ci[1], ci[2], ci[3],
                         A2[0][kk][0], A2[1][kk][0], A2[0][kk][1], A2[1][kk][1],
                         cur[2], cur[3]);
                mma16816(ci[4], ci[5], ci[6], ci[7],
                         A2[2][kk][0], A2[3][kk][0], A2[2][kk][1], A2[3][kk][1],
                         cur[2], cur[3]);
            }
#pragma unroll
            for (int rs = 0; rs < 4; rs++) {
                float r0 = cre_e[2*rs]   + cre_o[2*rs];
                float r1 = cre_e[2*rs+1] + cre_o[2*rs+1];
                float i0 = cim_e[2*rs]   + cim_o[2*rs];
                float i1 = cim_e[2*rs+1] + cim_o[2*rs+1];
                float p0 = r0 * r0 + i0 * i0;
                float p1 = r1 * r1 + i1 * i1;
                float d = p0 - p1, s = p0 + p1;
                z7a[rs] += d;
                Sc[rs] += s;
                z4a[rs] += (nt & 1) ? -s : s;
                z3a[rs] += (nt & 2) ? -s : s;
                z2a[rs] += (nt & 4) ? -s : s;
            }
        }

        // ---- per-unit epilogue: q-signs for z1/z0, quad-lane signs for z6/z5,
        //      butterfly over quad lanes, atomicAdd into out
#pragma unroll
        for (int rs = 0; rs < 4; rs++) {
            float z[8];
            z[0] = (q & 2) ? -Sc[rs] : Sc[rs];
            z[1] = (q & 1) ? -Sc[rs] : Sc[rs];
            z[2] = z2a[rs]; z[3] = z3a[rs]; z[4] = z4a[rs];
            z[5] = ((quad >> 1) & 1) ? -Sc[rs] : Sc[rs];
            z[6] = (quad & 1) ? -Sc[rs] : Sc[rs];
            z[7] = z7a[rs];
#pragma unroll
            for (int j = 0; j < 8; j++) {
                z[j] += __shfl_xor_sync(FULL, z[j], 1);
                z[j] += __shfl_xor_sync(FULL, z[j], 2);
            }
            const int row = base + qrow + rs * 8;
            atomicAdd(out + (size_t)row * 8 + 2 * quad,     z[2 * quad]);
            atomicAdd(out + (size_t)row * 8 + 2 * quad + 1, z[2 * quad + 1]);
        }
        __syncthreads();   // before next unit overwrites smB
    }
}

// ===================== host launcher =====================
extern "C" void kernel_launch(void* const* d_in, const int* in_sizes, int n_in,
                              void* d_out, int out_size) {
    const float* x    = (const float*)d_in[0];
    const float* conv = (const float*)d_in[1];
    const float* pool = (const float*)d_in[2];
    float* out = (float*)d_out;

    // zero output (accumulated via atomics)
    cudaMemsetAsync(d_out, 0, (size_t)out_size * sizeof(float), 0);

    build_u<<<128, 64>>>(conv, pool);

    static bool attr_set = false;
    if (!attr_set) {
        cudaFuncSetAttribute(qgemm, cudaFuncAttributeMaxDynamicSharedMemorySize, SMEM_TOTAL);
        attr_set = true;
    }

    cudaLaunchConfig_t cfg = {};
    cfg.gridDim = dim3(NCTA, 1, 1);
    cfg.blockDim = dim3(128, 1, 1);
    cfg.dynamicSmemBytes = SMEM_TOTAL;
    cfg.stream = 0;
    cudaLaunchAttribute attrs[1];
    attrs[0].id = cudaLaunchAttributeProgrammaticStreamSerialization;
    attrs[0].val.programmaticStreamSerializationAllowed = 1;
    cfg.attrs = attrs;
    cfg.numAttrs = 1;
    cudaLaunchKernelEx(&cfg, qgemm, x, out);
}